// round 3
// baseline (speedup 1.0000x reference)
#include <cuda_runtime.h>
#include <cstdint>

#define NN 50000
#define EE 500000
#define DD 128
#define HH 128
#define RR 3

// ---------------- device scratch (static, no runtime alloc) ----------------
__device__ float g_xbuf[NN * DD];   // dropped (and possibly permuted) input
__device__ float g_tmp[NN * DD];    // neg: dropped-before-permute
__device__ float g_agg[NN * DD];    // scatter-sum accumulator
__device__ float g_cnt[NN];         // degree counts
__device__ int g_perm[RR][NN];      // permutations per relation
// radix sort ping-pong buffers
__device__ unsigned g_ka[RR][NN];
__device__ unsigned g_kb[RR][NN];
__device__ int g_va[RR][NN];
__device__ int g_vb[RR][NN];

// ---------------- JAX threefry2x32 (exact, 20 rounds) ----------------
__host__ __device__ __forceinline__ void tf2x32(unsigned k0, unsigned k1,
                                                unsigned x0, unsigned x1,
                                                unsigned& o0, unsigned& o1) {
    unsigned ks0 = k0, ks1 = k1, ks2 = k0 ^ k1 ^ 0x1BD11BDAu;
    x0 += ks0; x1 += ks1;
#define TFR(r) { x0 += x1; x1 = (x1 << (r)) | (x1 >> (32 - (r))); x1 ^= x0; }
    TFR(13) TFR(15) TFR(26) TFR(6)   x0 += ks1; x1 += ks2 + 1u;
    TFR(17) TFR(29) TFR(16) TFR(24)  x0 += ks2; x1 += ks0 + 2u;
    TFR(13) TFR(15) TFR(26) TFR(6)   x0 += ks0; x1 += ks1 + 3u;
    TFR(17) TFR(29) TFR(16) TFR(24)  x0 += ks1; x1 += ks2 + 4u;
    TFR(13) TFR(15) TFR(26) TFR(6)   x0 += ks2; x1 += ks0 + 5u;
#undef TFR
    o0 = x0; o1 = x1;
}

// partitionable-mode random_bits (32-bit, index < 2^32): o0 ^ o1 of tf(key,(0,i))
__device__ __forceinline__ unsigned pbits(unsigned k0, unsigned k1, unsigned i) {
    unsigned o0, o1;
    tf2x32(k0, k1, 0u, i, o0, o1);
    return o0 ^ o1;
}

struct Keys6 { unsigned k[6]; };

// ---------------- permutation: sort-key generation ----------------
__global__ void keygen_kernel(Keys6 ks, int use_perm) {
    int r = blockIdx.y;
    unsigned k0 = ks.k[2 * r], k1 = ks.k[2 * r + 1];
    int i = blockIdx.x * blockDim.x + threadIdx.x;
    if (i >= NN) return;
    g_ka[r][i] = pbits(k0, k1, (unsigned)i);
    g_va[r][i] = use_perm ? g_perm[r][i] : i;
}

// ---------------- stable LSD radix sort (one block per relation) ----------------
// 256 threads, contiguous per-thread chunks; per-(thread,digit) u16 counts in
// dynamic smem (256*256*2 = 128KB). Stable by construction. Matches
// lax.sort_key_val (ascending, stable).
__global__ void sort_kernel() {
    extern __shared__ unsigned short scnt[];  // scnt[t*256 + d]
    __shared__ unsigned sbase[256];
    int r = blockIdx.x;
    int tid = threadIdx.x;
    const int T = 256;
    const int CH = (NN + T - 1) / T;  // 196
    int beg = tid * CH;
    int end = beg + CH; if (end > NN) end = NN;

    for (int pass = 0; pass < 4; pass++) {
        unsigned* ks = (pass & 1) ? g_kb[r] : g_ka[r];
        int* vs      = (pass & 1) ? g_vb[r] : g_va[r];
        unsigned* kd = (pass & 1) ? g_ka[r] : g_kb[r];
        int* vd      = (pass & 1) ? g_va[r] : g_vb[r];
        int sh = pass * 8;

        unsigned* sz = (unsigned*)scnt;
        for (int i = tid; i < T * 128; i += T) sz[i] = 0u;
        __syncthreads();

        for (int i = beg; i < end; i++) {
            unsigned d = (ks[i] >> sh) & 255u;
            scnt[tid * 256 + d]++;
        }
        __syncthreads();

        {
            unsigned d = tid, tot = 0;
            for (int t = 0; t < T; t++) {
                unsigned c = scnt[t * 256 + d];
                scnt[t * 256 + d] = (unsigned short)tot;
                tot += c;
            }
            sbase[d] = tot;
        }
        __syncthreads();
        if (tid == 0) {
            unsigned run = 0;
            for (int d = 0; d < 256; d++) { unsigned c = sbase[d]; sbase[d] = run; run += c; }
        }
        __syncthreads();

        for (int i = beg; i < end; i++) {
            unsigned k = ks[i];
            unsigned d = (k >> sh) & 255u;
            unsigned off = sbase[d] + (unsigned)scnt[tid * 256 + d];
            scnt[tid * 256 + d]++;
            kd[off] = k;
            vd[off] = vs[i];
        }
        __syncthreads();
    }
    for (int i = tid; i < NN; i += T) g_perm[r][i] = g_va[r][i];
}

// ---------------- dropout (exact partitionable bernoulli bits) ----------------
// uniform u = ((bits>>9)|0x3f800000) - 1; keep iff u < 0.5 iff bit31(bits)==0.
__global__ void drop_kernel(const float* __restrict__ x, float* __restrict__ y,
                            unsigned k0, unsigned k1) {
    int i4 = blockIdx.x * blockDim.x + threadIdx.x;  // over NN*DD/4
    if (i4 >= NN * DD / 4) return;
    unsigned base = (unsigned)i4 * 4u;
    float4 v = ((const float4*)x)[i4];
    float4 o;
    o.x = (pbits(k0, k1, base + 0u) & 0x80000000u) ? 0.f : 2.f * v.x;
    o.y = (pbits(k0, k1, base + 1u) & 0x80000000u) ? 0.f : 2.f * v.y;
    o.z = (pbits(k0, k1, base + 2u) & 0x80000000u) ? 0.f : 2.f * v.z;
    o.w = (pbits(k0, k1, base + 3u) & 0x80000000u) ? 0.f : 2.f * v.w;
    ((float4*)y)[i4] = o;
}

// ---------------- row permutation gather (neg path) ----------------
__global__ void permgather_kernel(const float* __restrict__ src,
                                  const int* __restrict__ perm,
                                  float* __restrict__ dst) {
    int i = blockIdx.x * blockDim.x + threadIdx.x;  // over NN*32 float4s
    if (i >= NN * 32) return;
    int row = i >> 5, c = i & 31;
    int p = perm[row];
    ((float4*)dst)[(size_t)row * 32 + c] = ((const float4*)src)[(size_t)p * 32 + c];
}

// ---------------- zero agg + cnt ----------------
__global__ void zero_kernel() {
    int i = blockIdx.x * blockDim.x + threadIdx.x;
    if (i < NN * DD / 4) ((float4*)g_agg)[i] = make_float4(0.f, 0.f, 0.f, 0.f);
    if (i < NN / 4) ((float4*)g_cnt)[i] = make_float4(0.f, 0.f, 0.f, 0.f);
}

// ---------------- edge gather + scatter-add (one warp per edge) ----------------
__global__ void edge_kernel(const int* __restrict__ ei, const float* __restrict__ xb) {
    int gw = (int)((blockIdx.x * blockDim.x + threadIdx.x) >> 5);
    int lane = threadIdx.x & 31;
    if (gw >= EE) return;
    int s = __ldg(ei + gw);
    int t = __ldg(ei + EE + gw);
    float4 v = ((const float4*)xb)[(size_t)s * 32 + lane];
    float* a = g_agg + (size_t)t * DD + lane * 4;
    atomicAdd(a + 0, v.x);
    atomicAdd(a + 1, v.y);
    atomicAdd(a + 2, v.z);
    atomicAdd(a + 3, v.w);
    if (lane == 0) atomicAdd(g_cnt + t, 1.f);
}

// ---------------- mean normalize ----------------
__global__ void norm_kernel() {
    int i = blockIdx.x * blockDim.x + threadIdx.x;
    if (i >= NN * 32) return;
    int row = i >> 5;
    float inv = 1.f / fmaxf(g_cnt[row], 1.f);
    float4 v = ((float4*)g_agg)[i];
    v.x *= inv; v.y *= inv; v.z *= inv; v.w *= inv;
    ((float4*)g_agg)[i] = v;
}

// ---------------- fused dual GEMM + bias + relu ----------------
// Y[N,H] = relu(g_agg @ W1 + X2 @ W2 + b). Tile 64(M) x 128(H), 256 threads.
__global__ void __launch_bounds__(256) gemm_kernel(const float* __restrict__ A2,
                                                   const float* __restrict__ W1,
                                                   const float* __restrict__ W2,
                                                   const float* __restrict__ bias,
                                                   float* __restrict__ O) {
    __shared__ float Ast[16][64];   // [k][m]
    __shared__ float Ws[16][128];   // [k][h]
    int tid = threadIdx.x;
    int m0 = blockIdx.x * 64;
    int tx = tid & 31, ty = tid >> 5;

    float acc[8][4];
#pragma unroll
    for (int i = 0; i < 8; i++)
#pragma unroll
        for (int j = 0; j < 4; j++) acc[i][j] = 0.f;

#pragma unroll 1
    for (int s = 0; s < 2; s++) {
        const float* A = s ? A2 : g_agg;
        const float* W = s ? W2 : W1;
#pragma unroll 1
        for (int kt = 0; kt < 8; kt++) {
            int ar = m0 + (tid >> 2);
            int ac = kt * 16 + (tid & 3) * 4;
            float4 av = make_float4(0.f, 0.f, 0.f, 0.f);
            if (ar < NN) av = *(const float4*)(A + (size_t)ar * DD + ac);
            int w0 = tid;
            int w1 = tid + 256;
            float4 wv0 = *(const float4*)(W + (size_t)(kt * 16 + (w0 >> 5)) * HH + (w0 & 31) * 4);
            float4 wv1 = *(const float4*)(W + (size_t)(kt * 16 + (w1 >> 5)) * HH + (w1 & 31) * 4);
            __syncthreads();
            {
                int rr = tid >> 2, cc = (tid & 3) * 4;
                Ast[cc + 0][rr] = av.x;
                Ast[cc + 1][rr] = av.y;
                Ast[cc + 2][rr] = av.z;
                Ast[cc + 3][rr] = av.w;
                *(float4*)&Ws[w0 >> 5][(w0 & 31) * 4] = wv0;
                *(float4*)&Ws[w1 >> 5][(w1 & 31) * 4] = wv1;
            }
            __syncthreads();
#pragma unroll
            for (int kk = 0; kk < 16; kk++) {
                float4 b = *(float4*)&Ws[kk][tx * 4];
                float4 a0 = *(float4*)&Ast[kk][ty * 8];
                float4 a1 = *(float4*)&Ast[kk][ty * 8 + 4];
                float aa[8] = {a0.x, a0.y, a0.z, a0.w, a1.x, a1.y, a1.z, a1.w};
#pragma unroll
                for (int i = 0; i < 8; i++) {
                    acc[i][0] += aa[i] * b.x;
                    acc[i][1] += aa[i] * b.y;
                    acc[i][2] += aa[i] * b.z;
                    acc[i][3] += aa[i] * b.w;
                }
            }
        }
    }

    float4 bb = *(const float4*)(bias + tx * 4);
#pragma unroll
    for (int i = 0; i < 8; i++) {
        int row = m0 + ty * 8 + i;
        if (row < NN) {
            float4 o;
            o.x = fmaxf(acc[i][0] + bb.x, 0.f);
            o.y = fmaxf(acc[i][1] + bb.y, 0.f);
            o.z = fmaxf(acc[i][2] + bb.z, 0.f);
            o.w = fmaxf(acc[i][3] + bb.w, 0.f);
            *(float4*)(O + (size_t)row * HH + tx * 4) = o;
        }
    }
}

// ---------------- host ----------------
extern "C" void kernel_launch(void* const* d_in, const int* in_sizes, int n_in,
                              void* d_out, int out_size) {
    const float* x = (const float*)d_in[0];
    const int* ei = (const int*)d_in[1];
    const float* Wl = (const float*)d_in[2];
    const float* bl = (const float*)d_in[3];
    const float* Wr = (const float*)d_in[4];
    float* out = (float*)d_out;
    (void)in_sizes; (void)n_in; (void)out_size;

    // ---- derive all JAX subkeys on host: PARTITIONABLE semantics ----
    // base = key(42) = (0,42)
    // fold_in(base, r)       = tf(base, (0, r))            -> full output = fkey
    // split(fkey, 3)[i]      = tf(fkey, (0, i))            -> (kp, kn, kperm)  [foldlike]
    // shuffle round 1: key1  = tf(kperm, (0,0)); use1 = tf(kperm, (0,1))
    // shuffle round 2: use2  = tf(key1,  (0,1))
    unsigned kp[RR][2], kn[RR][2], s1[RR][2], s2[RR][2];
    for (int r = 0; r < RR; r++) {
        unsigned f0, f1;
        tf2x32(0u, 42u, 0u, (unsigned)r, f0, f1);           // fold_in
        tf2x32(f0, f1, 0u, 0u, kp[r][0], kp[r][1]);         // split[0]
        tf2x32(f0, f1, 0u, 1u, kn[r][0], kn[r][1]);         // split[1]
        unsigned pk0, pk1;
        tf2x32(f0, f1, 0u, 2u, pk0, pk1);                   // split[2] = kperm
        unsigned key10, key11;
        tf2x32(pk0, pk1, 0u, 0u, key10, key11);             // round1 new key
        tf2x32(pk0, pk1, 0u, 1u, s1[r][0], s1[r][1]);       // round1 use_key
        tf2x32(key10, key11, 0u, 1u, s2[r][0], s2[r][1]);   // round2 use_key
    }

    cudaFuncSetAttribute(sort_kernel, cudaFuncAttributeMaxDynamicSharedMemorySize,
                         256 * 256 * 2);

    void *p_xbuf = nullptr, *p_tmp = nullptr, *p_perm = nullptr;
    cudaGetSymbolAddress(&p_xbuf, g_xbuf);
    cudaGetSymbolAddress(&p_tmp, g_tmp);
    cudaGetSymbolAddress(&p_perm, g_perm);
    float* xbuf = (float*)p_xbuf;
    float* tmp = (float*)p_tmp;
    int* perm = (int*)p_perm;

    // ---- permutations (2 stable-sort rounds, all relations in parallel) ----
    Keys6 K1, K2;
    for (int r = 0; r < RR; r++) {
        K1.k[2 * r] = s1[r][0]; K1.k[2 * r + 1] = s1[r][1];
        K2.k[2 * r] = s2[r][0]; K2.k[2 * r + 1] = s2[r][1];
    }
    dim3 kg((NN + 255) / 256, RR);
    keygen_kernel<<<kg, 256>>>(K1, 0);
    sort_kernel<<<RR, 256, 256 * 256 * 2>>>();
    keygen_kernel<<<kg, 256>>>(K2, 1);
    sort_kernel<<<RR, 256, 256 * 256 * 2>>>();

    const int dropBlocks = (NN * DD / 4 + 255) / 256;
    const int f4Blocks = (NN * DD / 4 + 255) / 256;
    const int rowBlocks = (NN * 32 + 255) / 256;
    const int edgeBlocks = (EE * 32 + 255) / 256;
    const int gemmBlocks = (NN + 63) / 64;

    for (int r = 0; r < RR; r++) {
        const int* eir = ei + (size_t)r * 2 * EE;
        const float* W1 = Wl + (size_t)r * DD * HH;
        const float* W2 = Wr + (size_t)r * DD * HH;
        const float* bb = bl + (size_t)r * HH;

        // ---- pos ----
        drop_kernel<<<dropBlocks, 256>>>(x, xbuf, kp[r][0], kp[r][1]);
        zero_kernel<<<f4Blocks, 256>>>();
        edge_kernel<<<edgeBlocks, 256>>>(eir, xbuf);
        norm_kernel<<<rowBlocks, 256>>>();
        gemm_kernel<<<gemmBlocks, 256>>>(xbuf, W1, W2, bb,
                                         out + (size_t)r * NN * HH);

        // ---- neg ----
        drop_kernel<<<dropBlocks, 256>>>(x, tmp, kn[r][0], kn[r][1]);
        permgather_kernel<<<rowBlocks, 256>>>(tmp, perm + r * NN, xbuf);
        zero_kernel<<<f4Blocks, 256>>>();
        edge_kernel<<<edgeBlocks, 256>>>(eir, xbuf);
        norm_kernel<<<rowBlocks, 256>>>();
        gemm_kernel<<<gemmBlocks, 256>>>(xbuf, W1, W2, bb,
                                         out + (size_t)(RR + r) * NN * HH);
    }
}

// round 6
// speedup vs baseline: 1.4298x; 1.4298x over previous
#include <cuda_runtime.h>
#include <cstdint>

#define NN 50000
#define EE 500000
#define DD 128
#define HH 128
#define RR 3

// ---------------- device scratch (static, no runtime alloc) ----------------
__device__ float g_xpos[NN * DD];
__device__ float g_xneg[NN * DD];
__device__ int g_inv[RR][NN];          // inverse permutations
// radix sort ping-pong buffers (g_va ends up holding the permutation)
__device__ unsigned g_ka[RR][NN];
__device__ unsigned g_kb[RR][NN];
__device__ int g_va[RR][NN];
__device__ int g_vb[RR][NN];
// CSR
__device__ int g_deg[RR][NN];
__device__ int g_fill[RR][NN];
__device__ int g_rowptr[RR][NN + 1];
__device__ int g_col[RR][EE];
__device__ unsigned g_bs[RR][64];
__device__ unsigned g_bo[RR][64];

// ---------------- JAX threefry2x32 (exact, 20 rounds) ----------------
__host__ __device__ __forceinline__ void tf2x32(unsigned k0, unsigned k1,
                                                unsigned x0, unsigned x1,
                                                unsigned& o0, unsigned& o1) {
    unsigned ks0 = k0, ks1 = k1, ks2 = k0 ^ k1 ^ 0x1BD11BDAu;
    x0 += ks0; x1 += ks1;
#define TFR(r) { x0 += x1; x1 = (x1 << (r)) | (x1 >> (32 - (r))); x1 ^= x0; }
    TFR(13) TFR(15) TFR(26) TFR(6)   x0 += ks1; x1 += ks2 + 1u;
    TFR(17) TFR(29) TFR(16) TFR(24)  x0 += ks2; x1 += ks0 + 2u;
    TFR(13) TFR(15) TFR(26) TFR(6)   x0 += ks0; x1 += ks1 + 3u;
    TFR(17) TFR(29) TFR(16) TFR(24)  x0 += ks1; x1 += ks2 + 4u;
    TFR(13) TFR(15) TFR(26) TFR(6)   x0 += ks2; x1 += ks0 + 5u;
#undef TFR
    o0 = x0; o1 = x1;
}

// partitionable-mode random_bits: o0 ^ o1 of tf(key,(0,i))
__device__ __forceinline__ unsigned pbits(unsigned k0, unsigned k1, unsigned i) {
    unsigned o0, o1;
    tf2x32(k0, k1, 0u, i, o0, o1);
    return o0 ^ o1;
}

struct Keys6 { unsigned k[6]; };

// ================= permutation machinery (R3-proven components) =================
__global__ void keygen_kernel(Keys6 ks, int init_iota) {
    int r = blockIdx.y;
    int i = blockIdx.x * blockDim.x + threadIdx.x;
    if (i >= NN) return;
    g_ka[r][i] = pbits(ks.k[2 * r], ks.k[2 * r + 1], (unsigned)i);
    if (init_iota) g_va[r][i] = i;  // round 2 keeps round-1 result in g_va
}

// stable LSD radix sort, one block per relation (PROVEN in Round 3).
// 256 threads, contiguous per-thread chunks, per-(thread,digit) u16 counts.
__global__ void sort_kernel() {
    extern __shared__ unsigned short scnt[];  // scnt[t*256 + d]
    __shared__ unsigned sbase[256];
    int r = blockIdx.x;
    int tid = threadIdx.x;
    const int T = 256;
    const int CH = (NN + T - 1) / T;  // 196
    int beg = tid * CH;
    int end = beg + CH; if (end > NN) end = NN;

    for (int pass = 0; pass < 4; pass++) {
        unsigned* ks = (pass & 1) ? g_kb[r] : g_ka[r];
        int* vs      = (pass & 1) ? g_vb[r] : g_va[r];
        unsigned* kd = (pass & 1) ? g_ka[r] : g_kb[r];
        int* vd      = (pass & 1) ? g_va[r] : g_vb[r];
        int sh = pass * 8;

        unsigned* sz = (unsigned*)scnt;
        for (int i = tid; i < T * 128; i += T) sz[i] = 0u;
        __syncthreads();

        for (int i = beg; i < end; i++) {
            unsigned d = (ks[i] >> sh) & 255u;
            scnt[tid * 256 + d]++;
        }
        __syncthreads();

        {
            unsigned d = tid, tot = 0;
            for (int t = 0; t < T; t++) {
                unsigned c = scnt[t * 256 + d];
                scnt[t * 256 + d] = (unsigned short)tot;
                tot += c;
            }
            sbase[d] = tot;
        }
        __syncthreads();
        if (tid == 0) {
            unsigned run = 0;
            for (int d = 0; d < 256; d++) { unsigned c = sbase[d]; sbase[d] = run; run += c; }
        }
        __syncthreads();

        for (int i = beg; i < end; i++) {
            unsigned k = ks[i];
            unsigned d = (k >> sh) & 255u;
            unsigned off = sbase[d] + (unsigned)scnt[tid * 256 + d];
            scnt[tid * 256 + d]++;
            kd[off] = k;
            vd[off] = vs[i];
        }
        __syncthreads();
    }
    // 4 passes -> result resides in g_va
}

__global__ void invperm_kernel() {
    int r = blockIdx.y;
    int i = blockIdx.x * blockDim.x + threadIdx.x;
    if (i >= NN) return;
    g_inv[r][g_va[r][i]] = i;
}

// ================= CSR build =================
__global__ void csr_zero() {
    int i = blockIdx.x * blockDim.x + threadIdx.x;
    if (i < RR * NN) { ((int*)g_deg)[i] = 0; ((int*)g_fill)[i] = 0; }
}
__global__ void csr_hist(const int* __restrict__ ei) {
    int idx = blockIdx.x * blockDim.x + threadIdx.x;
    if (idx >= RR * EE) return;
    int r = idx / EE, e = idx - r * EE;
    int t = __ldg(ei + (size_t)r * 2 * EE + EE + e);
    atomicAdd(&g_deg[r][t], 1);
}
__global__ void scan1() {
    __shared__ unsigned s[1024];
    int r = blockIdx.y, b = blockIdx.x, tid = threadIdx.x;
    int i = b * 1024 + tid;
    unsigned v = (i < NN) ? (unsigned)g_deg[r][i] : 0u;
    s[tid] = v;
    __syncthreads();
    unsigned incl = v;
    for (int o = 1; o < 1024; o <<= 1) {
        unsigned add = (tid >= o) ? s[tid - o] : 0u;
        __syncthreads();
        incl += add; s[tid] = incl;
        __syncthreads();
    }
    if (i < NN) g_rowptr[r][i + 1] = (int)incl;
    if (tid == 1023) g_bs[r][b] = incl;
}
__global__ void scan2(int nb) {
    int r = blockIdx.x;
    if (threadIdx.x == 0) {
        unsigned run = 0;
        for (int b = 0; b < nb; b++) { unsigned t = g_bs[r][b]; g_bo[r][b] = run; run += t; }
    }
}
__global__ void scan3() {
    int r = blockIdx.y, b = blockIdx.x;
    int i = b * 1024 + threadIdx.x;
    if (i < NN) g_rowptr[r][i + 1] += (int)g_bo[r][b];
    if (b == 0 && threadIdx.x == 0) g_rowptr[r][0] = 0;
}
__global__ void csr_fill(const int* __restrict__ ei) {
    int idx = blockIdx.x * blockDim.x + threadIdx.x;
    if (idx >= RR * EE) return;
    int r = idx / EE, e = idx - r * EE;
    int s = __ldg(ei + (size_t)r * 2 * EE + e);
    int t = __ldg(ei + (size_t)r * 2 * EE + EE + e);
    int p = g_rowptr[r][t] + atomicAdd(&g_fill[r][t], 1);
    g_col[r][p] = s;
}

// ================= fused pos+neg dropout (+ permutation scatter) =================
__global__ void dropboth_kernel(const float* __restrict__ x, const int* __restrict__ inv,
                                unsigned kp0, unsigned kp1, unsigned kn0, unsigned kn1) {
    int i4 = blockIdx.x * blockDim.x + threadIdx.x;
    if (i4 >= NN * 32) return;
    int row = i4 >> 5, c = i4 & 31;
    float4 v = ((const float4*)x)[i4];
    unsigned base = (unsigned)i4 * 4u;
    float4 p, n;
    p.x = (pbits(kp0, kp1, base + 0u) & 0x80000000u) ? 0.f : 2.f * v.x;
    p.y = (pbits(kp0, kp1, base + 1u) & 0x80000000u) ? 0.f : 2.f * v.y;
    p.z = (pbits(kp0, kp1, base + 2u) & 0x80000000u) ? 0.f : 2.f * v.z;
    p.w = (pbits(kp0, kp1, base + 3u) & 0x80000000u) ? 0.f : 2.f * v.w;
    n.x = (pbits(kn0, kn1, base + 0u) & 0x80000000u) ? 0.f : 2.f * v.x;
    n.y = (pbits(kn0, kn1, base + 1u) & 0x80000000u) ? 0.f : 2.f * v.y;
    n.z = (pbits(kn0, kn1, base + 2u) & 0x80000000u) ? 0.f : 2.f * v.z;
    n.w = (pbits(kn0, kn1, base + 3u) & 0x80000000u) ? 0.f : 2.f * v.w;
    ((float4*)g_xpos)[i4] = p;
    ((float4*)g_xneg)[(size_t)inv[row] * 32 + c] = n;  // neg[i] = dropped(x)[perm[i]]
}

// ================= fused CSR-aggregate + mean + dual GEMM + bias + relu ============
// smem: As[64][128] agg tile | Xs[64][128] own x rows | Ws[16][128] W stage
__global__ void __launch_bounds__(256) agg_gemm_kernel(
        const float* __restrict__ xb, const int* __restrict__ rowptr,
        const int* __restrict__ colidx, const float* __restrict__ W1,
        const float* __restrict__ W2, const float* __restrict__ bias,
        float* __restrict__ O) {
    extern __shared__ float sm[];
    float* As = sm;
    float* Xs = sm + 64 * 128;
    float* Ws = sm + 2 * 64 * 128;
    int tid = threadIdx.x, lane = tid & 31, w = tid >> 5;
    int m0 = blockIdx.x * 64;
    const float4* xb4 = (const float4*)xb;

    // load own x rows
    float4* Xs4 = (float4*)Xs;
    for (int i = tid; i < 64 * 32; i += 256) {
        int rr = i >> 5, cc = i & 31, row = m0 + rr;
        Xs4[i] = (row < NN) ? xb4[(size_t)row * 32 + cc] : make_float4(0.f, 0.f, 0.f, 0.f);
    }
    // aggregate (warp per row, 8 rows per warp), mean folded in
    float4* As4 = (float4*)As;
    for (int j = 0; j < 8; j++) {
        int rr = w * 8 + j, row = m0 + rr;
        float4 acc = make_float4(0.f, 0.f, 0.f, 0.f);
        if (row < NN) {
            int beg = __ldg(rowptr + row), end = __ldg(rowptr + row + 1);
            int e = beg;
            for (; e + 4 <= end; e += 4) {
                int s0 = __ldg(colidx + e), s1 = __ldg(colidx + e + 1);
                int s2 = __ldg(colidx + e + 2), s3 = __ldg(colidx + e + 3);
                float4 v0 = xb4[(size_t)s0 * 32 + lane];
                float4 v1 = xb4[(size_t)s1 * 32 + lane];
                float4 v2 = xb4[(size_t)s2 * 32 + lane];
                float4 v3 = xb4[(size_t)s3 * 32 + lane];
                acc.x += v0.x + v1.x + v2.x + v3.x;
                acc.y += v0.y + v1.y + v2.y + v3.y;
                acc.z += v0.z + v1.z + v2.z + v3.z;
                acc.w += v0.w + v1.w + v2.w + v3.w;
            }
            for (; e < end; e++) {
                int s = __ldg(colidx + e);
                float4 v = xb4[(size_t)s * 32 + lane];
                acc.x += v.x; acc.y += v.y; acc.z += v.z; acc.w += v.w;
            }
            float inv = 1.f / fmaxf((float)(end - beg), 1.f);
            acc.x *= inv; acc.y *= inv; acc.z *= inv; acc.w *= inv;
        }
        As4[rr * 32 + lane] = acc;
    }
    __syncthreads();

    // GEMM: acc = As @ W1 + Xs @ W2
    float acc[8][4];
#pragma unroll
    for (int i = 0; i < 8; i++)
#pragma unroll
        for (int j = 0; j < 4; j++) acc[i][j] = 0.f;
    int tx = tid & 31, ty = tid >> 5;

#pragma unroll 1
    for (int s = 0; s < 2; s++) {
        const float* SRC = s ? Xs : As;
        const float* W = s ? W2 : W1;
#pragma unroll 1
        for (int kt = 0; kt < 8; kt++) {
            int w0 = tid, w1 = tid + 256;
            float4 wv0 = *(const float4*)(W + (size_t)(kt * 16 + (w0 >> 5)) * HH + (w0 & 31) * 4);
            float4 wv1 = *(const float4*)(W + (size_t)(kt * 16 + (w1 >> 5)) * HH + (w1 & 31) * 4);
            __syncthreads();
            *(float4*)&Ws[(w0 >> 5) * 128 + (w0 & 31) * 4] = wv0;
            *(float4*)&Ws[(w1 >> 5) * 128 + (w1 & 31) * 4] = wv1;
            __syncthreads();
#pragma unroll
            for (int kk = 0; kk < 16; kk += 4) {
                float4 a4[8];
#pragma unroll
                for (int i = 0; i < 8; i++)
                    a4[i] = *(const float4*)&SRC[(ty * 8 + i) * 128 + kt * 16 + kk];  // warp broadcast
#pragma unroll
                for (int j = 0; j < 4; j++) {
                    float4 b = *(const float4*)&Ws[(kk + j) * 128 + tx * 4];
#pragma unroll
                    for (int i = 0; i < 8; i++) {
                        float a = (j == 0) ? a4[i].x : (j == 1) ? a4[i].y : (j == 2) ? a4[i].z : a4[i].w;
                        acc[i][0] += a * b.x;
                        acc[i][1] += a * b.y;
                        acc[i][2] += a * b.z;
                        acc[i][3] += a * b.w;
                    }
                }
            }
        }
    }

    float4 bb = *(const float4*)(bias + tx * 4);
#pragma unroll
    for (int i = 0; i < 8; i++) {
        int row = m0 + ty * 8 + i;
        if (row < NN) {
            float4 o;
            o.x = fmaxf(acc[i][0] + bb.x, 0.f);
            o.y = fmaxf(acc[i][1] + bb.y, 0.f);
            o.z = fmaxf(acc[i][2] + bb.z, 0.f);
            o.w = fmaxf(acc[i][3] + bb.w, 0.f);
            *(float4*)(O + (size_t)row * HH + tx * 4) = o;
        }
    }
}

// ---------------- host ----------------
extern "C" void kernel_launch(void* const* d_in, const int* in_sizes, int n_in,
                              void* d_out, int out_size) {
    const float* x = (const float*)d_in[0];
    const int* ei = (const int*)d_in[1];
    const float* Wl = (const float*)d_in[2];
    const float* bl = (const float*)d_in[3];
    const float* Wr = (const float*)d_in[4];
    float* out = (float*)d_out;
    (void)in_sizes; (void)n_in; (void)out_size;

    // ---- derive all JAX subkeys on host (partitionable semantics) ----
    unsigned kp[RR][2], kn[RR][2], s1k[RR][2], s2k[RR][2];
    for (int r = 0; r < RR; r++) {
        unsigned f0, f1;
        tf2x32(0u, 42u, 0u, (unsigned)r, f0, f1);           // fold_in
        tf2x32(f0, f1, 0u, 0u, kp[r][0], kp[r][1]);         // split[0]
        tf2x32(f0, f1, 0u, 1u, kn[r][0], kn[r][1]);         // split[1]
        unsigned pk0, pk1;
        tf2x32(f0, f1, 0u, 2u, pk0, pk1);                   // split[2] = kperm
        unsigned key10, key11;
        tf2x32(pk0, pk1, 0u, 0u, key10, key11);             // round1 new key
        tf2x32(pk0, pk1, 0u, 1u, s1k[r][0], s1k[r][1]);     // round1 use key
        tf2x32(key10, key11, 0u, 1u, s2k[r][0], s2k[r][1]); // round2 use key
    }

    // set attributes unconditionally every call (no static guards)
    cudaFuncSetAttribute(sort_kernel, cudaFuncAttributeMaxDynamicSharedMemorySize, 131072);
    cudaFuncSetAttribute(agg_gemm_kernel, cudaFuncAttributeMaxDynamicSharedMemorySize, 73728);

    void *p_xpos = nullptr, *p_xneg = nullptr, *p_inv = nullptr;
    void *p_rowptr = nullptr, *p_col = nullptr;
    cudaGetSymbolAddress(&p_xpos, g_xpos);
    cudaGetSymbolAddress(&p_xneg, g_xneg);
    cudaGetSymbolAddress(&p_inv, g_inv);
    cudaGetSymbolAddress(&p_rowptr, g_rowptr);
    cudaGetSymbolAddress(&p_col, g_col);
    float* xpos = (float*)p_xpos;
    float* xneg = (float*)p_xneg;
    int* invp = (int*)p_inv;
    int* rowptr = (int*)p_rowptr;
    int* colidx = (int*)p_col;

    // ---- CSR build (once per launch) ----
    const int NB = (NN + 1023) / 1024;  // 49
    csr_zero<<<(RR * NN + 255) / 256, 256>>>();
    csr_hist<<<(RR * EE + 255) / 256, 256>>>(ei);
    scan1<<<dim3(NB, RR), 1024>>>();
    scan2<<<RR, 32>>>(NB);
    scan3<<<dim3(NB, RR), 1024>>>();
    csr_fill<<<(RR * EE + 255) / 256, 256>>>(ei);

    // ---- permutations: 2 rounds of stable sort (R3-proven single-block sort) ----
    Keys6 K1, K2;
    for (int r = 0; r < RR; r++) {
        K1.k[2 * r] = s1k[r][0]; K1.k[2 * r + 1] = s1k[r][1];
        K2.k[2 * r] = s2k[r][0]; K2.k[2 * r + 1] = s2k[r][1];
    }
    dim3 kg((NN + 255) / 256, RR);
    keygen_kernel<<<kg, 256>>>(K1, 1);
    sort_kernel<<<RR, 256, 131072>>>();
    keygen_kernel<<<kg, 256>>>(K2, 0);
    sort_kernel<<<RR, 256, 131072>>>();
    invperm_kernel<<<kg, 256>>>();

    // ---- per-relation pipeline ----
    const int dropBlocks = (NN * 32 + 255) / 256;
    const int gemmBlocks = (NN + 63) / 64;
    for (int r = 0; r < RR; r++) {
        const float* W1 = Wl + (size_t)r * DD * HH;
        const float* W2 = Wr + (size_t)r * DD * HH;
        const float* bb = bl + (size_t)r * HH;
        dropboth_kernel<<<dropBlocks, 256>>>(x, invp + (size_t)r * NN,
                                             kp[r][0], kp[r][1], kn[r][0], kn[r][1]);
        agg_gemm_kernel<<<gemmBlocks, 256, 73728>>>(
            xpos, rowptr + (size_t)r * (NN + 1), colidx + (size_t)r * EE,
            W1, W2, bb, out + (size_t)r * NN * HH);
        agg_gemm_kernel<<<gemmBlocks, 256, 73728>>>(
            xneg, rowptr + (size_t)r * (NN + 1), colidx + (size_t)r * EE,
            W1, W2, bb, out + (size_t)(RR + r) * NN * HH);
    }
}

// round 8
// speedup vs baseline: 1.9187x; 1.3419x over previous
#include <cuda_runtime.h>
#include <cstdint>

#define NN 50000
#define EE 500000
#define DD 128
#define HH 128
#define RR 3

// ---------------- device scratch (static, no runtime alloc) ----------------
__device__ float g_xpos[NN * DD];
__device__ float g_xneg[NN * DD];
__device__ int g_inv[RR][NN];          // inverse of final permutation
// radix sort ping-pong buffers, per round x relation (g_va ends with argsort)
__device__ unsigned g_ka[2][RR][NN];
__device__ unsigned g_kb[2][RR][NN];
__device__ int g_va[2][RR][NN];
__device__ int g_vb[2][RR][NN];
// CSR
__device__ int g_deg[RR][NN];
__device__ int g_fill[RR][NN];
__device__ int g_rowptr[RR][NN + 1];
__device__ int g_col[RR][EE];
__device__ unsigned g_bs[RR][64];
__device__ unsigned g_bo[RR][64];

// ---------------- JAX threefry2x32 (exact, 20 rounds) ----------------
__host__ __device__ __forceinline__ void tf2x32(unsigned k0, unsigned k1,
                                                unsigned x0, unsigned x1,
                                                unsigned& o0, unsigned& o1) {
    unsigned ks0 = k0, ks1 = k1, ks2 = k0 ^ k1 ^ 0x1BD11BDAu;
    x0 += ks0; x1 += ks1;
#define TFR(r) { x0 += x1; x1 = (x1 << (r)) | (x1 >> (32 - (r))); x1 ^= x0; }
    TFR(13) TFR(15) TFR(26) TFR(6)   x0 += ks1; x1 += ks2 + 1u;
    TFR(17) TFR(29) TFR(16) TFR(24)  x0 += ks2; x1 += ks0 + 2u;
    TFR(13) TFR(15) TFR(26) TFR(6)   x0 += ks0; x1 += ks1 + 3u;
    TFR(17) TFR(29) TFR(16) TFR(24)  x0 += ks1; x1 += ks2 + 4u;
    TFR(13) TFR(15) TFR(26) TFR(6)   x0 += ks2; x1 += ks0 + 5u;
#undef TFR
    o0 = x0; o1 = x1;
}

// partitionable-mode random_bits: o0 ^ o1 of tf(key,(0,i))
__device__ __forceinline__ unsigned pbits(unsigned k0, unsigned k1, unsigned i) {
    unsigned o0, o1;
    tf2x32(k0, k1, 0u, i, o0, o1);
    return o0 ^ o1;
}

struct Keys12 { unsigned k[12]; };  // [round*6 + r*2 + {0,1}]

// ================= permutation machinery =================
// Generate sort keys for BOTH shuffle rounds (independent of each other).
__global__ void keygen_kernel(Keys12 ks) {
    int r = blockIdx.y, round = blockIdx.z;
    int i = blockIdx.x * blockDim.x + threadIdx.x;
    if (i >= NN) return;
    unsigned k0 = ks.k[round * 6 + 2 * r], k1 = ks.k[round * 6 + 2 * r + 1];
    g_ka[round][r][i] = pbits(k0, k1, (unsigned)i);
    g_va[round][r][i] = i;  // both rounds sort (keys, iota) -> argsort
}

// stable LSD radix sort, one block per (relation, round) — R3/R6-proven body.
// 256 threads, contiguous per-thread chunks, per-(thread,digit) u16 counts.
__global__ void sort_kernel() {
    extern __shared__ unsigned short scnt[];  // scnt[t*256 + d]
    __shared__ unsigned sbase[256];
    int r = blockIdx.x, round = blockIdx.y;
    int tid = threadIdx.x;
    const int T = 256;
    const int CH = (NN + T - 1) / T;  // 196
    int beg = tid * CH;
    int end = beg + CH; if (end > NN) end = NN;

    for (int pass = 0; pass < 4; pass++) {
        unsigned* ks = (pass & 1) ? g_kb[round][r] : g_ka[round][r];
        int* vs      = (pass & 1) ? g_vb[round][r] : g_va[round][r];
        unsigned* kd = (pass & 1) ? g_ka[round][r] : g_kb[round][r];
        int* vd      = (pass & 1) ? g_va[round][r] : g_vb[round][r];
        int sh = pass * 8;

        unsigned* sz = (unsigned*)scnt;
        for (int i = tid; i < T * 128; i += T) sz[i] = 0u;
        __syncthreads();

        for (int i = beg; i < end; i++) {
            unsigned d = (ks[i] >> sh) & 255u;
            scnt[tid * 256 + d]++;
        }
        __syncthreads();

        {
            unsigned d = tid, tot = 0;
            for (int t = 0; t < T; t++) {
                unsigned c = scnt[t * 256 + d];
                scnt[t * 256 + d] = (unsigned short)tot;
                tot += c;
            }
            sbase[d] = tot;
        }
        __syncthreads();
        if (tid == 0) {
            unsigned run = 0;
            for (int d = 0; d < 256; d++) { unsigned c = sbase[d]; sbase[d] = run; run += c; }
        }
        __syncthreads();

        for (int i = beg; i < end; i++) {
            unsigned k = ks[i];
            unsigned d = (k >> sh) & 255u;
            unsigned off = sbase[d] + (unsigned)scnt[tid * 256 + d];
            scnt[tid * 256 + d]++;
            kd[off] = k;
            vd[off] = vs[i];
        }
        __syncthreads();
    }
    // 4 passes -> argsort resides in g_va[round][r]
}

// compose the two rounds and invert: final p[j] = a1[a2[j]]; inv[p[j]] = j
__global__ void compose_invperm_kernel() {
    int r = blockIdx.y;
    int j = blockIdx.x * blockDim.x + threadIdx.x;
    if (j >= NN) return;
    int a2 = g_va[1][r][j];
    int p = g_va[0][r][a2];
    g_inv[r][p] = j;
}

// ================= CSR build =================
__global__ void csr_zero() {
    int i = blockIdx.x * blockDim.x + threadIdx.x;
    if (i < RR * NN) { ((int*)g_deg)[i] = 0; ((int*)g_fill)[i] = 0; }
}
__global__ void csr_hist(const int* __restrict__ ei) {
    int idx = blockIdx.x * blockDim.x + threadIdx.x;
    if (idx >= RR * EE) return;
    int r = idx / EE, e = idx - r * EE;
    int t = __ldg(ei + (size_t)r * 2 * EE + EE + e);
    atomicAdd(&g_deg[r][t], 1);
}
__global__ void scan1() {
    __shared__ unsigned s[1024];
    int r = blockIdx.y, b = blockIdx.x, tid = threadIdx.x;
    int i = b * 1024 + tid;
    unsigned v = (i < NN) ? (unsigned)g_deg[r][i] : 0u;
    s[tid] = v;
    __syncthreads();
    unsigned incl = v;
    for (int o = 1; o < 1024; o <<= 1) {
        unsigned add = (tid >= o) ? s[tid - o] : 0u;
        __syncthreads();
        incl += add; s[tid] = incl;
        __syncthreads();
    }
    if (i < NN) g_rowptr[r][i + 1] = (int)incl;
    if (tid == 1023) g_bs[r][b] = incl;
}
__global__ void scan2(int nb) {
    int r = blockIdx.x;
    if (threadIdx.x == 0) {
        unsigned run = 0;
        for (int b = 0; b < nb; b++) { unsigned t = g_bs[r][b]; g_bo[r][b] = run; run += t; }
    }
}
__global__ void scan3() {
    int r = blockIdx.y, b = blockIdx.x;
    int i = b * 1024 + threadIdx.x;
    if (i < NN) g_rowptr[r][i + 1] += (int)g_bo[r][b];
    if (b == 0 && threadIdx.x == 0) g_rowptr[r][0] = 0;
}
__global__ void csr_fill(const int* __restrict__ ei) {
    int idx = blockIdx.x * blockDim.x + threadIdx.x;
    if (idx >= RR * EE) return;
    int r = idx / EE, e = idx - r * EE;
    int s = __ldg(ei + (size_t)r * 2 * EE + e);
    int t = __ldg(ei + (size_t)r * 2 * EE + EE + e);
    int p = g_rowptr[r][t] + atomicAdd(&g_fill[r][t], 1);
    g_col[r][p] = s;
}

// ================= fused pos+neg dropout (+ permutation scatter) =================
__global__ void dropboth_kernel(const float* __restrict__ x, const int* __restrict__ inv,
                                unsigned kp0, unsigned kp1, unsigned kn0, unsigned kn1) {
    int i4 = blockIdx.x * blockDim.x + threadIdx.x;
    if (i4 >= NN * 32) return;
    int row = i4 >> 5, c = i4 & 31;
    float4 v = ((const float4*)x)[i4];
    unsigned base = (unsigned)i4 * 4u;
    float4 p, n;
    p.x = (pbits(kp0, kp1, base + 0u) & 0x80000000u) ? 0.f : 2.f * v.x;
    p.y = (pbits(kp0, kp1, base + 1u) & 0x80000000u) ? 0.f : 2.f * v.y;
    p.z = (pbits(kp0, kp1, base + 2u) & 0x80000000u) ? 0.f : 2.f * v.z;
    p.w = (pbits(kp0, kp1, base + 3u) & 0x80000000u) ? 0.f : 2.f * v.w;
    n.x = (pbits(kn0, kn1, base + 0u) & 0x80000000u) ? 0.f : 2.f * v.x;
    n.y = (pbits(kn0, kn1, base + 1u) & 0x80000000u) ? 0.f : 2.f * v.y;
    n.z = (pbits(kn0, kn1, base + 2u) & 0x80000000u) ? 0.f : 2.f * v.z;
    n.w = (pbits(kn0, kn1, base + 3u) & 0x80000000u) ? 0.f : 2.f * v.w;
    ((float4*)g_xpos)[i4] = p;
    ((float4*)g_xneg)[(size_t)inv[row] * 32 + c] = n;  // neg[i] = dropped(x)[perm[i]]
}

// ================= fused CSR-aggregate + mean + dual GEMM + bias + relu ============
// smem: As[64][128] agg tile | Xs[64][128] own x rows | Ws[16][128] W stage
__global__ void __launch_bounds__(256) agg_gemm_kernel(
        const float* __restrict__ xb, const int* __restrict__ rowptr,
        const int* __restrict__ colidx, const float* __restrict__ W1,
        const float* __restrict__ W2, const float* __restrict__ bias,
        float* __restrict__ O) {
    extern __shared__ float sm[];
    float* As = sm;
    float* Xs = sm + 64 * 128;
    float* Ws = sm + 2 * 64 * 128;
    int tid = threadIdx.x, lane = tid & 31, w = tid >> 5;
    int m0 = blockIdx.x * 64;
    const float4* xb4 = (const float4*)xb;

    // load own x rows
    float4* Xs4 = (float4*)Xs;
    for (int i = tid; i < 64 * 32; i += 256) {
        int rr = i >> 5, cc = i & 31, row = m0 + rr;
        Xs4[i] = (row < NN) ? xb4[(size_t)row * 32 + cc] : make_float4(0.f, 0.f, 0.f, 0.f);
    }
    // aggregate (warp per row, 8 rows per warp), mean folded in
    float4* As4 = (float4*)As;
    for (int j = 0; j < 8; j++) {
        int rr = w * 8 + j, row = m0 + rr;
        float4 acc = make_float4(0.f, 0.f, 0.f, 0.f);
        if (row < NN) {
            int beg = __ldg(rowptr + row), end = __ldg(rowptr + row + 1);
            int e = beg;
            for (; e + 4 <= end; e += 4) {
                int s0 = __ldg(colidx + e), s1 = __ldg(colidx + e + 1);
                int s2 = __ldg(colidx + e + 2), s3 = __ldg(colidx + e + 3);
                float4 v0 = xb4[(size_t)s0 * 32 + lane];
                float4 v1 = xb4[(size_t)s1 * 32 + lane];
                float4 v2 = xb4[(size_t)s2 * 32 + lane];
                float4 v3 = xb4[(size_t)s3 * 32 + lane];
                acc.x += v0.x + v1.x + v2.x + v3.x;
                acc.y += v0.y + v1.y + v2.y + v3.y;
                acc.z += v0.z + v1.z + v2.z + v3.z;
                acc.w += v0.w + v1.w + v2.w + v3.w;
            }
            for (; e < end; e++) {
                int s = __ldg(colidx + e);
                float4 v = xb4[(size_t)s * 32 + lane];
                acc.x += v.x; acc.y += v.y; acc.z += v.z; acc.w += v.w;
            }
            float inv = 1.f / fmaxf((float)(end - beg), 1.f);
            acc.x *= inv; acc.y *= inv; acc.z *= inv; acc.w *= inv;
        }
        As4[rr * 32 + lane] = acc;
    }
    __syncthreads();

    // GEMM: acc = As @ W1 + Xs @ W2
    float acc[8][4];
#pragma unroll
    for (int i = 0; i < 8; i++)
#pragma unroll
        for (int j = 0; j < 4; j++) acc[i][j] = 0.f;
    int tx = tid & 31, ty = tid >> 5;

#pragma unroll 1
    for (int s = 0; s < 2; s++) {
        const float* SRC = s ? Xs : As;
        const float* W = s ? W2 : W1;
#pragma unroll 1
        for (int kt = 0; kt < 8; kt++) {
            int w0 = tid, w1 = tid + 256;
            float4 wv0 = *(const float4*)(W + (size_t)(kt * 16 + (w0 >> 5)) * HH + (w0 & 31) * 4);
            float4 wv1 = *(const float4*)(W + (size_t)(kt * 16 + (w1 >> 5)) * HH + (w1 & 31) * 4);
            __syncthreads();
            *(float4*)&Ws[(w0 >> 5) * 128 + (w0 & 31) * 4] = wv0;
            *(float4*)&Ws[(w1 >> 5) * 128 + (w1 & 31) * 4] = wv1;
            __syncthreads();
#pragma unroll
            for (int kk = 0; kk < 16; kk += 4) {
                float4 a4[8];
#pragma unroll
                for (int i = 0; i < 8; i++)
                    a4[i] = *(const float4*)&SRC[(ty * 8 + i) * 128 + kt * 16 + kk];  // warp broadcast
#pragma unroll
                for (int j = 0; j < 4; j++) {
                    float4 b = *(const float4*)&Ws[(kk + j) * 128 + tx * 4];
#pragma unroll
                    for (int i = 0; i < 8; i++) {
                        float a = (j == 0) ? a4[i].x : (j == 1) ? a4[i].y : (j == 2) ? a4[i].z : a4[i].w;
                        acc[i][0] += a * b.x;
                        acc[i][1] += a * b.y;
                        acc[i][2] += a * b.z;
                        acc[i][3] += a * b.w;
                    }
                }
            }
        }
    }

    float4 bb = *(const float4*)(bias + tx * 4);
#pragma unroll
    for (int i = 0; i < 8; i++) {
        int row = m0 + ty * 8 + i;
        if (row < NN) {
            float4 o;
            o.x = fmaxf(acc[i][0] + bb.x, 0.f);
            o.y = fmaxf(acc[i][1] + bb.y, 0.f);
            o.z = fmaxf(acc[i][2] + bb.z, 0.f);
            o.w = fmaxf(acc[i][3] + bb.w, 0.f);
            *(float4*)(O + (size_t)row * HH + tx * 4) = o;
        }
    }
}

// ---------------- host ----------------
extern "C" void kernel_launch(void* const* d_in, const int* in_sizes, int n_in,
                              void* d_out, int out_size) {
    const float* x = (const float*)d_in[0];
    const int* ei = (const int*)d_in[1];
    const float* Wl = (const float*)d_in[2];
    const float* bl = (const float*)d_in[3];
    const float* Wr = (const float*)d_in[4];
    float* out = (float*)d_out;
    (void)in_sizes; (void)n_in; (void)out_size;

    // ---- derive all JAX subkeys on host (partitionable semantics) ----
    unsigned kp[RR][2], kn[RR][2], s1k[RR][2], s2k[RR][2];
    for (int r = 0; r < RR; r++) {
        unsigned f0, f1;
        tf2x32(0u, 42u, 0u, (unsigned)r, f0, f1);           // fold_in
        tf2x32(f0, f1, 0u, 0u, kp[r][0], kp[r][1]);         // split[0]
        tf2x32(f0, f1, 0u, 1u, kn[r][0], kn[r][1]);         // split[1]
        unsigned pk0, pk1;
        tf2x32(f0, f1, 0u, 2u, pk0, pk1);                   // split[2] = kperm
        unsigned key10, key11;
        tf2x32(pk0, pk1, 0u, 0u, key10, key11);             // round1 new key
        tf2x32(pk0, pk1, 0u, 1u, s1k[r][0], s1k[r][1]);     // round1 use key
        tf2x32(key10, key11, 0u, 1u, s2k[r][0], s2k[r][1]); // round2 use key
    }

    // set attributes unconditionally every call (no static guards)
    cudaFuncSetAttribute(sort_kernel, cudaFuncAttributeMaxDynamicSharedMemorySize, 131072);
    cudaFuncSetAttribute(agg_gemm_kernel, cudaFuncAttributeMaxDynamicSharedMemorySize, 73728);

    void *p_xpos = nullptr, *p_xneg = nullptr, *p_inv = nullptr;
    void *p_rowptr = nullptr, *p_col = nullptr;
    cudaGetSymbolAddress(&p_xpos, g_xpos);
    cudaGetSymbolAddress(&p_xneg, g_xneg);
    cudaGetSymbolAddress(&p_inv, g_inv);
    cudaGetSymbolAddress(&p_rowptr, g_rowptr);
    cudaGetSymbolAddress(&p_col, g_col);
    float* xpos = (float*)p_xpos;
    float* xneg = (float*)p_xneg;
    int* invp = (int*)p_inv;
    int* rowptr = (int*)p_rowptr;
    int* colidx = (int*)p_col;

    // ---- CSR build (once per launch) ----
    const int NB = (NN + 1023) / 1024;  // 49
    csr_zero<<<(RR * NN + 255) / 256, 256>>>();
    csr_hist<<<(RR * EE + 255) / 256, 256>>>(ei);
    scan1<<<dim3(NB, RR), 1024>>>();
    scan2<<<RR, 32>>>(NB);
    scan3<<<dim3(NB, RR), 1024>>>();
    csr_fill<<<(RR * EE + 255) / 256, 256>>>(ei);

    // ---- permutations: BOTH rounds' argsorts computed concurrently, then composed.
    // final perm p[j] = a1[a2[j]] (round-2 sort reorders round-1's output, and the
    // round-2 ranks depend only on round-2 keys). One sort launch, grid (RR, 2).
    Keys12 KK;
    for (int r = 0; r < RR; r++) {
        KK.k[0 + 2 * r] = s1k[r][0]; KK.k[0 + 2 * r + 1] = s1k[r][1];
        KK.k[6 + 2 * r] = s2k[r][0]; KK.k[6 + 2 * r + 1] = s2k[r][1];
    }
    dim3 kg((NN + 255) / 256, RR, 2);
    keygen_kernel<<<kg, 256>>>(KK);
    sort_kernel<<<dim3(RR, 2), 256, 131072>>>();
    dim3 cg((NN + 255) / 256, RR);
    compose_invperm_kernel<<<cg, 256>>>();

    // ---- per-relation pipeline ----
    const int dropBlocks = (NN * 32 + 255) / 256;
    const int gemmBlocks = (NN + 63) / 64;
    for (int r = 0; r < RR; r++) {
        const float* W1 = Wl + (size_t)r * DD * HH;
        const float* W2 = Wr + (size_t)r * DD * HH;
        const float* bb = bl + (size_t)r * HH;
        dropboth_kernel<<<dropBlocks, 256>>>(x, invp + (size_t)r * NN,
                                             kp[r][0], kp[r][1], kn[r][0], kn[r][1]);
        agg_gemm_kernel<<<gemmBlocks, 256, 73728>>>(
            xpos, rowptr + (size_t)r * (NN + 1), colidx + (size_t)r * EE,
            W1, W2, bb, out + (size_t)r * NN * HH);
        agg_gemm_kernel<<<gemmBlocks, 256, 73728>>>(
            xneg, rowptr + (size_t)r * (NN + 1), colidx + (size_t)r * EE,
            W1, W2, bb, out + (size_t)(RR + r) * NN * HH);
    }
}

// round 9
// speedup vs baseline: 2.9373x; 1.5309x over previous
#include <cuda_runtime.h>
#include <cstdint>

#define NN 50000
#define EE 500000
#define DD 128
#define HH 128
#define RR 3
#define NBKT 1024   // MSD buckets (top 10 bits)

// ---------------- device scratch (static, no runtime alloc) ----------------
__device__ float g_xpos[NN * DD];
__device__ float g_xneg[NN * DD];
__device__ int g_inv[RR][NN];                       // inverse of final permutation
// MSD bucket machinery, per round x relation
__device__ unsigned g_key[2][RR][NN];
__device__ unsigned long long g_pairs[2][RR][NN];   // (key<<32)|idx
__device__ int g_arg[2][RR][NN];                    // argsort result per round
__device__ int g_bhist[2][RR][NBKT];
__device__ int g_bfill[2][RR][NBKT];
__device__ int g_bstart[2][RR][NBKT + 1];
// CSR
__device__ int g_deg[RR][NN];
__device__ int g_fill[RR][NN];
__device__ int g_rowptr[RR][NN + 1];
__device__ int g_col[RR][EE];
__device__ unsigned g_bs[RR][64];
__device__ unsigned g_bo[RR][64];

// ---------------- JAX threefry2x32 (exact, 20 rounds) ----------------
__host__ __device__ __forceinline__ void tf2x32(unsigned k0, unsigned k1,
                                                unsigned x0, unsigned x1,
                                                unsigned& o0, unsigned& o1) {
    unsigned ks0 = k0, ks1 = k1, ks2 = k0 ^ k1 ^ 0x1BD11BDAu;
    x0 += ks0; x1 += ks1;
#define TFR(r) { x0 += x1; x1 = (x1 << (r)) | (x1 >> (32 - (r))); x1 ^= x0; }
    TFR(13) TFR(15) TFR(26) TFR(6)   x0 += ks1; x1 += ks2 + 1u;
    TFR(17) TFR(29) TFR(16) TFR(24)  x0 += ks2; x1 += ks0 + 2u;
    TFR(13) TFR(15) TFR(26) TFR(6)   x0 += ks0; x1 += ks1 + 3u;
    TFR(17) TFR(29) TFR(16) TFR(24)  x0 += ks1; x1 += ks2 + 4u;
    TFR(13) TFR(15) TFR(26) TFR(6)   x0 += ks2; x1 += ks0 + 5u;
#undef TFR
    o0 = x0; o1 = x1;
}

// partitionable-mode random_bits: o0 ^ o1 of tf(key,(0,i))
__device__ __forceinline__ unsigned pbits(unsigned k0, unsigned k1, unsigned i) {
    unsigned o0, o1;
    tf2x32(k0, k1, 0u, i, o0, o1);
    return o0 ^ o1;
}

struct Keys12 { unsigned k[12]; };  // [round*6 + r*2 + {0,1}]

// ================= permutation machinery: MSD buckets + counting rank ==========
// Stable sort_key_val(keys, iota) == order by unique u64 (key<<32 | idx).
// No stage below needs to be stable; the idx tiebreak recovers stability.

__global__ void bzero_kernel() {
    int i = blockIdx.x * blockDim.x + threadIdx.x;
    if (i < 2 * RR * NBKT) {
        ((int*)g_bhist)[i] = 0;
        ((int*)g_bfill)[i] = 0;
    }
}

// key generation + bucket histogram (top 10 bits)
__global__ void keyhist_kernel(Keys12 ks) {
    int r = blockIdx.y, round = blockIdx.z;
    int i = blockIdx.x * blockDim.x + threadIdx.x;
    if (i >= NN) return;
    unsigned k0 = ks.k[round * 6 + 2 * r], k1 = ks.k[round * 6 + 2 * r + 1];
    unsigned key = pbits(k0, k1, (unsigned)i);
    g_key[round][r][i] = key;
    atomicAdd(&g_bhist[round][r][key >> 22], 1);
}

// exclusive prefix over the 1024 buckets of one (round, relation)
__global__ void bprefix_kernel() {
    __shared__ unsigned s[NBKT];
    int r = blockIdx.x, round = blockIdx.y, tid = threadIdx.x;
    unsigned v = (unsigned)g_bhist[round][r][tid];
    s[tid] = v;
    __syncthreads();
    unsigned incl = v;
    for (int o = 1; o < NBKT; o <<= 1) {
        unsigned add = (tid >= o) ? s[tid - o] : 0u;
        __syncthreads();
        incl += add; s[tid] = incl;
        __syncthreads();
    }
    g_bstart[round][r][tid + 1] = (int)incl;
    if (tid == 0) g_bstart[round][r][0] = 0;
}

// unordered scatter of (key, idx) pairs into buckets
__global__ void bscatter_kernel() {
    int r = blockIdx.y, round = blockIdx.z;
    int i = blockIdx.x * blockDim.x + threadIdx.x;
    if (i >= NN) return;
    unsigned key = g_key[round][r][i];
    int b = (int)(key >> 22);
    int pos = g_bstart[round][r][b] + atomicAdd(&g_bfill[round][r][b], 1);
    g_pairs[round][r][pos] = ((unsigned long long)key << 32) | (unsigned)i;
}

// one warp per bucket: rank each pair by counting strictly-smaller pairs.
// u64 pairs are unique (idx unique) -> exact total order, any bucket size OK.
__global__ void brank_kernel() {
    int gwarp = (blockIdx.x * blockDim.x + threadIdx.x) >> 5;
    int lane = threadIdx.x & 31;
    if (gwarp >= 2 * RR * NBKT) return;
    int round = gwarp / (RR * NBKT);
    int rem = gwarp - round * RR * NBKT;
    int r = rem >> 10, b = rem & (NBKT - 1);
    int base = g_bstart[round][r][b];
    int end = g_bstart[round][r][b + 1];
    int m = end - base;
    const unsigned long long* P = g_pairs[round][r];
    int* A = g_arg[round][r];
    for (int e = lane; e < m; e += 32) {
        unsigned long long me = P[base + e];
        int cnt = 0;
        for (int j = 0; j < m; j++) cnt += (P[base + j] < me) ? 1 : 0;
        A[base + cnt] = (int)(me & 0xffffffffu);
    }
}

// compose the two rounds and invert: final p[j] = a1[a2[j]]; inv[p[j]] = j
__global__ void compose_invperm_kernel() {
    int r = blockIdx.y;
    int j = blockIdx.x * blockDim.x + threadIdx.x;
    if (j >= NN) return;
    int a2 = g_arg[1][r][j];
    int p = g_arg[0][r][a2];
    g_inv[r][p] = j;
}

// ================= CSR build =================
__global__ void csr_zero() {
    int i = blockIdx.x * blockDim.x + threadIdx.x;
    if (i < RR * NN) { ((int*)g_deg)[i] = 0; ((int*)g_fill)[i] = 0; }
}
__global__ void csr_hist(const int* __restrict__ ei) {
    int idx = blockIdx.x * blockDim.x + threadIdx.x;
    if (idx >= RR * EE) return;
    int r = idx / EE, e = idx - r * EE;
    int t = __ldg(ei + (size_t)r * 2 * EE + EE + e);
    atomicAdd(&g_deg[r][t], 1);
}
__global__ void scan1() {
    __shared__ unsigned s[1024];
    int r = blockIdx.y, b = blockIdx.x, tid = threadIdx.x;
    int i = b * 1024 + tid;
    unsigned v = (i < NN) ? (unsigned)g_deg[r][i] : 0u;
    s[tid] = v;
    __syncthreads();
    unsigned incl = v;
    for (int o = 1; o < 1024; o <<= 1) {
        unsigned add = (tid >= o) ? s[tid - o] : 0u;
        __syncthreads();
        incl += add; s[tid] = incl;
        __syncthreads();
    }
    if (i < NN) g_rowptr[r][i + 1] = (int)incl;
    if (tid == 1023) g_bs[r][b] = incl;
}
__global__ void scan2(int nb) {
    int r = blockIdx.x;
    if (threadIdx.x == 0) {
        unsigned run = 0;
        for (int b = 0; b < nb; b++) { unsigned t = g_bs[r][b]; g_bo[r][b] = run; run += t; }
    }
}
__global__ void scan3() {
    int r = blockIdx.y, b = blockIdx.x;
    int i = b * 1024 + threadIdx.x;
    if (i < NN) g_rowptr[r][i + 1] += (int)g_bo[r][b];
    if (b == 0 && threadIdx.x == 0) g_rowptr[r][0] = 0;
}
__global__ void csr_fill(const int* __restrict__ ei) {
    int idx = blockIdx.x * blockDim.x + threadIdx.x;
    if (idx >= RR * EE) return;
    int r = idx / EE, e = idx - r * EE;
    int s = __ldg(ei + (size_t)r * 2 * EE + e);
    int t = __ldg(ei + (size_t)r * 2 * EE + EE + e);
    int p = g_rowptr[r][t] + atomicAdd(&g_fill[r][t], 1);
    g_col[r][p] = s;
}

// ================= fused pos+neg dropout (+ permutation scatter) =================
__global__ void dropboth_kernel(const float* __restrict__ x, const int* __restrict__ inv,
                                unsigned kp0, unsigned kp1, unsigned kn0, unsigned kn1) {
    int i4 = blockIdx.x * blockDim.x + threadIdx.x;
    if (i4 >= NN * 32) return;
    int row = i4 >> 5, c = i4 & 31;
    float4 v = ((const float4*)x)[i4];
    unsigned base = (unsigned)i4 * 4u;
    float4 p, n;
    p.x = (pbits(kp0, kp1, base + 0u) & 0x80000000u) ? 0.f : 2.f * v.x;
    p.y = (pbits(kp0, kp1, base + 1u) & 0x80000000u) ? 0.f : 2.f * v.y;
    p.z = (pbits(kp0, kp1, base + 2u) & 0x80000000u) ? 0.f : 2.f * v.z;
    p.w = (pbits(kp0, kp1, base + 3u) & 0x80000000u) ? 0.f : 2.f * v.w;
    n.x = (pbits(kn0, kn1, base + 0u) & 0x80000000u) ? 0.f : 2.f * v.x;
    n.y = (pbits(kn0, kn1, base + 1u) & 0x80000000u) ? 0.f : 2.f * v.y;
    n.z = (pbits(kn0, kn1, base + 2u) & 0x80000000u) ? 0.f : 2.f * v.z;
    n.w = (pbits(kn0, kn1, base + 3u) & 0x80000000u) ? 0.f : 2.f * v.w;
    ((float4*)g_xpos)[i4] = p;
    ((float4*)g_xneg)[(size_t)inv[row] * 32 + c] = n;  // neg[i] = dropped(x)[perm[i]]
}

// ================= fused CSR-aggregate + mean + dual GEMM + bias + relu ============
// smem: As[64][128] agg tile | Xs[64][128] own x rows | Ws[16][128] W stage
__global__ void __launch_bounds__(256) agg_gemm_kernel(
        const float* __restrict__ xb, const int* __restrict__ rowptr,
        const int* __restrict__ colidx, const float* __restrict__ W1,
        const float* __restrict__ W2, const float* __restrict__ bias,
        float* __restrict__ O) {
    extern __shared__ float sm[];
    float* As = sm;
    float* Xs = sm + 64 * 128;
    float* Ws = sm + 2 * 64 * 128;
    int tid = threadIdx.x, lane = tid & 31, w = tid >> 5;
    int m0 = blockIdx.x * 64;
    const float4* xb4 = (const float4*)xb;

    // load own x rows
    float4* Xs4 = (float4*)Xs;
    for (int i = tid; i < 64 * 32; i += 256) {
        int rr = i >> 5, cc = i & 31, row = m0 + rr;
        Xs4[i] = (row < NN) ? xb4[(size_t)row * 32 + cc] : make_float4(0.f, 0.f, 0.f, 0.f);
    }
    // aggregate (warp per row, 8 rows per warp), mean folded in
    float4* As4 = (float4*)As;
    for (int j = 0; j < 8; j++) {
        int rr = w * 8 + j, row = m0 + rr;
        float4 acc = make_float4(0.f, 0.f, 0.f, 0.f);
        if (row < NN) {
            int beg = __ldg(rowptr + row), end = __ldg(rowptr + row + 1);
            int e = beg;
            for (; e + 4 <= end; e += 4) {
                int s0 = __ldg(colidx + e), s1 = __ldg(colidx + e + 1);
                int s2 = __ldg(colidx + e + 2), s3 = __ldg(colidx + e + 3);
                float4 v0 = xb4[(size_t)s0 * 32 + lane];
                float4 v1 = xb4[(size_t)s1 * 32 + lane];
                float4 v2 = xb4[(size_t)s2 * 32 + lane];
                float4 v3 = xb4[(size_t)s3 * 32 + lane];
                acc.x += v0.x + v1.x + v2.x + v3.x;
                acc.y += v0.y + v1.y + v2.y + v3.y;
                acc.z += v0.z + v1.z + v2.z + v3.z;
                acc.w += v0.w + v1.w + v2.w + v3.w;
            }
            for (; e < end; e++) {
                int s = __ldg(colidx + e);
                float4 v = xb4[(size_t)s * 32 + lane];
                acc.x += v.x; acc.y += v.y; acc.z += v.z; acc.w += v.w;
            }
            float inv = 1.f / fmaxf((float)(end - beg), 1.f);
            acc.x *= inv; acc.y *= inv; acc.z *= inv; acc.w *= inv;
        }
        As4[rr * 32 + lane] = acc;
    }
    __syncthreads();

    // GEMM: acc = As @ W1 + Xs @ W2
    float acc[8][4];
#pragma unroll
    for (int i = 0; i < 8; i++)
#pragma unroll
        for (int j = 0; j < 4; j++) acc[i][j] = 0.f;
    int tx = tid & 31, ty = tid >> 5;

#pragma unroll 1
    for (int s = 0; s < 2; s++) {
        const float* SRC = s ? Xs : As;
        const float* W = s ? W2 : W1;
#pragma unroll 1
        for (int kt = 0; kt < 8; kt++) {
            int w0 = tid, w1 = tid + 256;
            float4 wv0 = *(const float4*)(W + (size_t)(kt * 16 + (w0 >> 5)) * HH + (w0 & 31) * 4);
            float4 wv1 = *(const float4*)(W + (size_t)(kt * 16 + (w1 >> 5)) * HH + (w1 & 31) * 4);
            __syncthreads();
            *(float4*)&Ws[(w0 >> 5) * 128 + (w0 & 31) * 4] = wv0;
            *(float4*)&Ws[(w1 >> 5) * 128 + (w1 & 31) * 4] = wv1;
            __syncthreads();
#pragma unroll
            for (int kk = 0; kk < 16; kk += 4) {
                float4 a4[8];
#pragma unroll
                for (int i = 0; i < 8; i++)
                    a4[i] = *(const float4*)&SRC[(ty * 8 + i) * 128 + kt * 16 + kk];  // warp broadcast
#pragma unroll
                for (int j = 0; j < 4; j++) {
                    float4 b = *(const float4*)&Ws[(kk + j) * 128 + tx * 4];
#pragma unroll
                    for (int i = 0; i < 8; i++) {
                        float a = (j == 0) ? a4[i].x : (j == 1) ? a4[i].y : (j == 2) ? a4[i].z : a4[i].w;
                        acc[i][0] += a * b.x;
                        acc[i][1] += a * b.y;
                        acc[i][2] += a * b.z;
                        acc[i][3] += a * b.w;
                    }
                }
            }
        }
    }

    float4 bb = *(const float4*)(bias + tx * 4);
#pragma unroll
    for (int i = 0; i < 8; i++) {
        int row = m0 + ty * 8 + i;
        if (row < NN) {
            float4 o;
            o.x = fmaxf(acc[i][0] + bb.x, 0.f);
            o.y = fmaxf(acc[i][1] + bb.y, 0.f);
            o.z = fmaxf(acc[i][2] + bb.z, 0.f);
            o.w = fmaxf(acc[i][3] + bb.w, 0.f);
            *(float4*)(O + (size_t)row * HH + tx * 4) = o;
        }
    }
}

// ---------------- host ----------------
extern "C" void kernel_launch(void* const* d_in, const int* in_sizes, int n_in,
                              void* d_out, int out_size) {
    const float* x = (const float*)d_in[0];
    const int* ei = (const int*)d_in[1];
    const float* Wl = (const float*)d_in[2];
    const float* bl = (const float*)d_in[3];
    const float* Wr = (const float*)d_in[4];
    float* out = (float*)d_out;
    (void)in_sizes; (void)n_in; (void)out_size;

    // ---- derive all JAX subkeys on host (partitionable semantics) ----
    unsigned kp[RR][2], kn[RR][2], s1k[RR][2], s2k[RR][2];
    for (int r = 0; r < RR; r++) {
        unsigned f0, f1;
        tf2x32(0u, 42u, 0u, (unsigned)r, f0, f1);           // fold_in
        tf2x32(f0, f1, 0u, 0u, kp[r][0], kp[r][1]);         // split[0]
        tf2x32(f0, f1, 0u, 1u, kn[r][0], kn[r][1]);         // split[1]
        unsigned pk0, pk1;
        tf2x32(f0, f1, 0u, 2u, pk0, pk1);                   // split[2] = kperm
        unsigned key10, key11;
        tf2x32(pk0, pk1, 0u, 0u, key10, key11);             // round1 new key
        tf2x32(pk0, pk1, 0u, 1u, s1k[r][0], s1k[r][1]);     // round1 use key
        tf2x32(key10, key11, 0u, 1u, s2k[r][0], s2k[r][1]); // round2 use key
    }

    // set attributes unconditionally every call (no static guards)
    cudaFuncSetAttribute(agg_gemm_kernel, cudaFuncAttributeMaxDynamicSharedMemorySize, 73728);

    void *p_xpos = nullptr, *p_xneg = nullptr, *p_inv = nullptr;
    void *p_rowptr = nullptr, *p_col = nullptr;
    cudaGetSymbolAddress(&p_xpos, g_xpos);
    cudaGetSymbolAddress(&p_xneg, g_xneg);
    cudaGetSymbolAddress(&p_inv, g_inv);
    cudaGetSymbolAddress(&p_rowptr, g_rowptr);
    cudaGetSymbolAddress(&p_col, g_col);
    float* xpos = (float*)p_xpos;
    float* xneg = (float*)p_xneg;
    int* invp = (int*)p_inv;
    int* rowptr = (int*)p_rowptr;
    int* colidx = (int*)p_col;

    // ---- CSR build (once per launch) ----
    const int NB = (NN + 1023) / 1024;  // 49
    csr_zero<<<(RR * NN + 255) / 256, 256>>>();
    csr_hist<<<(RR * EE + 255) / 256, 256>>>(ei);
    scan1<<<dim3(NB, RR), 1024>>>();
    scan2<<<RR, 32>>>(NB);
    scan3<<<dim3(NB, RR), 1024>>>();
    csr_fill<<<(RR * EE + 255) / 256, 256>>>(ei);

    // ---- permutations: MSD buckets + counting rank (both rounds concurrent) ----
    Keys12 KK;
    for (int r = 0; r < RR; r++) {
        KK.k[0 + 2 * r] = s1k[r][0]; KK.k[0 + 2 * r + 1] = s1k[r][1];
        KK.k[6 + 2 * r] = s2k[r][0]; KK.k[6 + 2 * r + 1] = s2k[r][1];
    }
    dim3 eg((NN + 255) / 256, RR, 2);
    bzero_kernel<<<(2 * RR * NBKT + 255) / 256, 256>>>();
    keyhist_kernel<<<eg, 256>>>(KK);
    bprefix_kernel<<<dim3(RR, 2), NBKT>>>();
    bscatter_kernel<<<eg, 256>>>();
    brank_kernel<<<(2 * RR * NBKT * 32 + 255) / 256, 256>>>();
    dim3 cg((NN + 255) / 256, RR);
    compose_invperm_kernel<<<cg, 256>>>();

    // ---- per-relation pipeline ----
    const int dropBlocks = (NN * 32 + 255) / 256;
    const int gemmBlocks = (NN + 63) / 64;
    for (int r = 0; r < RR; r++) {
        const float* W1 = Wl + (size_t)r * DD * HH;
        const float* W2 = Wr + (size_t)r * DD * HH;
        const float* bb = bl + (size_t)r * HH;
        dropboth_kernel<<<dropBlocks, 256>>>(x, invp + (size_t)r * NN,
                                             kp[r][0], kp[r][1], kn[r][0], kn[r][1]);
        agg_gemm_kernel<<<gemmBlocks, 256, 73728>>>(
            xpos, rowptr + (size_t)r * (NN + 1), colidx + (size_t)r * EE,
            W1, W2, bb, out + (size_t)r * NN * HH);
        agg_gemm_kernel<<<gemmBlocks, 256, 73728>>>(
            xneg, rowptr + (size_t)r * (NN + 1), colidx + (size_t)r * EE,
            W1, W2, bb, out + (size_t)(RR + r) * NN * HH);
    }
}